// round 13
// baseline (speedup 1.0000x reference)
#include <cuda_runtime.h>
#include <cuda_bf16.h>

// Entmax15: out = clip(X - tau*, 0)^2 with sum(out) = 1 per row,
// X = (masked_scores - rowmax) * 0.5.
//
// tau* via Newton on g(tau) = sqrt(f(tau)) - 1, f(tau) = sum max(X-tau,0)^2.
// g is convex left of the root (each piece of f is K(t-c)^2+v so
// 2 f f'' - f'^2 = 4Kv >= 0, g' continuous nondecreasing), hence Newton from
// tau = -1 is monotone and never overshoots: dlt = (S2 - sqrt(S2)) / S1.
//
// Frozen structure (R8/R12, DRAM 85.6%): 128 thr x 16 elem, 1 row/CTA,
// 8 front-batched LDG.128/thread, one barrier per solve iteration, tau
// bitwise-uniform across the block (no exit broadcast), double-buffered
// warp partials. R9/R10/R11: multi-row overlap, cp.async staging, and L2
// prefetch all regressed — structure stays.
//
// R13 delta: shorten the solve-iteration critical path. Warp shuffle reduce
// goes 5 levels -> 3 levels (octet reduce, offsets 4/2/1, ~-52 cyc of serial
// SHFL latency); 16 octet leaders (lane%8==0) STS (S1,S2); after the single
// barrier every thread combines the 16 partials via 8 LDS.128 + FADD tree.
// Change is entirely after the load/extract block -> LDG batching untouched.
// redux.sync.f32 unavailable on sm_103a (R5) -> shuffle-based reduce.

constexpr int S_LEN   = 2048;
constexpr int THREADS = 128;
constexpr int WARPS   = THREADS / 32;
constexpr int OCTETS  = THREADS / 8;          // 16 octet leaders
constexpr int EPT     = S_LEN / THREADS;      // 16 elems per thread
constexpr int V4      = EPT / 4;              // 4 float4 per thread
constexpr float NEG_FILL = -1e4f;

__global__ void __launch_bounds__(THREADS, 8)
entmax15_kernel(const float* __restrict__ scores,
                const int*   __restrict__ mask,
                float*       __restrict__ out)
{
    const long long base = (long long)blockIdx.x * S_LEN;
    const float4* s4 = reinterpret_cast<const float4*>(scores + base);
    const int4*   m4 = reinterpret_cast<const int4*>(mask + base);
    float4*       o4 = reinterpret_cast<float4*>(out + base);

    const int tid  = threadIdx.x;
    const int warp = tid >> 5;
    const int lane = tid & 31;

    // ---- load 16 elems/thread (front-batched), apply mask ----
    float x[EPT];
    #pragma unroll
    for (int v = 0; v < V4; ++v) {
        float4 a = s4[tid + v * THREADS];
        int4   m = m4[tid + v * THREADS];
        x[v * 4 + 0] = m.x ? a.x : NEG_FILL;
        x[v * 4 + 1] = m.y ? a.y : NEG_FILL;
        x[v * 4 + 2] = m.z ? a.z : NEG_FILL;
        x[v * 4 + 3] = m.w ? a.w : NEG_FILL;
    }

    __shared__ float  shmax[WARPS];
    __shared__ float2 red[2][OCTETS];   // double-buffered (S1,S2) per octet

    // ---- block max (runs once; keep full 5-level warp reduce) ----
    float mx = x[0];
    #pragma unroll
    for (int i = 1; i < EPT; ++i) mx = fmaxf(mx, x[i]);
    #pragma unroll
    for (int o = 16; o; o >>= 1) mx = fmaxf(mx, __shfl_xor_sync(0xffffffffu, mx, o));
    if (lane == 0) shmax[warp] = mx;
    __syncthreads();
    mx = fmaxf(fmaxf(shmax[0], shmax[1]), fmaxf(shmax[2], shmax[3]));

    // ---- alpha=1.5 transform: X = (x - max) * 0.5 so max(X) == 0 ----
    const float mxh = mx * 0.5f;
    #pragma unroll
    for (int i = 0; i < EPT; ++i) x[i] = fmaf(x[i], 0.5f, -mxh);

    // ---- Newton-on-sqrt root find; tau* in [-1, 0) ----
    float tau = -1.0f;   // the max element alone contributes 1 => f(-1) >= 1
    int   p   = 0;
    const int octet = tid >> 3;          // 0..15

    #pragma unroll 1
    for (int it = 0; it < 20; ++it) {
        float s1a = 0.0f, s1b = 0.0f, s2a = 0.0f, s2b = 0.0f;
        #pragma unroll
        for (int i = 0; i < EPT; i += 2) {
            float d0 = fmaxf(x[i]     - tau, 0.0f);
            float d1 = fmaxf(x[i + 1] - tau, 0.0f);
            s1a += d0;                s1b += d1;
            s2a  = fmaf(d0, d0, s2a); s2b  = fmaf(d1, d1, s2b);
        }
        float s1 = s1a + s1b;
        float s2 = s2a + s2b;
        // 3-level octet reduce (offsets 4,2,1 stay within each 8-lane octet)
        #pragma unroll
        for (int o = 4; o; o >>= 1) {
            s1 += __shfl_xor_sync(0xffffffffu, s1, o);
            s2 += __shfl_xor_sync(0xffffffffu, s2, o);
        }
        if ((lane & 7) == 0) red[p][octet] = make_float2(s1, s2);
        __syncthreads();

        // combine 16 (S1,S2) partials: 8 LDS.128, FADD tree
        const float4* r4 = reinterpret_cast<const float4*>(red[p]);
        float S1 = 0.0f, S2 = 0.0f;
        {
            float4 q0 = r4[0], q1 = r4[1], q2 = r4[2], q3 = r4[3];
            float4 q4 = r4[4], q5 = r4[5], q6 = r4[6], q7 = r4[7];
            float a1 = ((q0.x + q0.z) + (q1.x + q1.z)) + ((q2.x + q2.z) + (q3.x + q3.z));
            float b1 = ((q4.x + q4.z) + (q5.x + q5.z)) + ((q6.x + q6.z) + (q7.x + q7.z));
            float a2 = ((q0.y + q0.w) + (q1.y + q1.w)) + ((q2.y + q2.w) + (q3.y + q3.w));
            float b2 = ((q4.y + q4.w) + (q5.y + q5.w)) + ((q6.y + q6.w) + (q7.y + q7.w));
            S1 = a1 + b1;
            S2 = a2 + b2;
        }
        p ^= 1;

        // Newton on sqrt(f)-1: dlt = (S2 - sqrt(S2)) / S1.
        // Uniform inputs + uniform ops -> tau identical across all threads.
        float dlt = __fdividef(S2 - sqrtf(S2), fmaxf(S1, 1e-20f));
        tau += dlt;
        if (dlt < 1e-6f) break;
    }

    // ---- emit p = clip(X - tau, 0)^2 ----
    #pragma unroll
    for (int v = 0; v < V4; ++v) {
        float4 r;
        float d;
        d = fmaxf(x[v * 4 + 0] - tau, 0.0f); r.x = d * d;
        d = fmaxf(x[v * 4 + 1] - tau, 0.0f); r.y = d * d;
        d = fmaxf(x[v * 4 + 2] - tau, 0.0f); r.z = d * d;
        d = fmaxf(x[v * 4 + 3] - tau, 0.0f); r.w = d * d;
        o4[tid + v * THREADS] = r;
    }
}

extern "C" void kernel_launch(void* const* d_in, const int* in_sizes, int n_in,
                              void* d_out, int out_size)
{
    const float* scores = (const float*)d_in[0];
    const int*   mask   = (const int*)d_in[1];
    float*       out    = (float*)d_out;
    const int rows = in_sizes[0] / S_LEN;
    entmax15_kernel<<<rows, THREADS>>>(scores, mask, out);
}

// round 14
// speedup vs baseline: 1.1164x; 1.1164x over previous
#include <cuda_runtime.h>
#include <cuda_bf16.h>

// Entmax15: out = clip(X - tau*, 0)^2 with sum(out) = 1 per row,
// X = (masked_scores - rowmax) * 0.5.
//
// tau* via Newton on g(tau) = sqrt(f(tau)) - 1, f(tau) = sum max(X-tau,0)^2.
// g is convex left of the root (each piece of f is K(t-c)^2+v so
// 2 f f'' - f'^2 = 4Kv >= 0, g' continuous nondecreasing), hence Newton from
// tau = -1 is monotone and never overshoots: dlt = (S2 - sqrt(S2)) / S1.
//
// FINAL (= R8; best measured twice: 116.9/117.2us bench, 111.6us ncu,
// HBM 6784 GB/s = 85.6% of spec moving exactly the mandatory 768 MB —
// the mixed 2:1 read:write stream ceiling on this part):
//  - 128 threads x 16 elems/row, 1 row/CTA: 8 front-batched LDG.128/thread
//    at 40 regs / ~71% occupancy. Measured lessons: per-thread front-batched
//    LDG depth drives HBM BW (R7); ANY edit that raises regs (R9: 72, R13:
//    62), stages through smem (R10), or injects code between the load batch
//    and extract (R11) reduces achieved BW more than it gains.
//  - ONE barrier per solve iteration: warp leaders STS (S1,S2) into a
//    double-buffered slot; every thread combines the 4 warp partials and
//    computes tau locally. Identical FP ops on identical inputs => tau is
//    bitwise-uniform across the block => loop exit needs no broadcast.
//    Double buffering makes the single-barrier scheme race-free.
//  - redux.sync.f32 unavailable on sm_103a (R5) -> shuffle-tree warp reduce.

constexpr int S_LEN   = 2048;
constexpr int THREADS = 128;
constexpr int WARPS   = THREADS / 32;
constexpr int EPT     = S_LEN / THREADS;      // 16 elems per thread
constexpr int V4      = EPT / 4;              // 4 float4 per thread
constexpr float NEG_FILL = -1e4f;

__global__ void __launch_bounds__(THREADS, 8)
entmax15_kernel(const float* __restrict__ scores,
                const int*   __restrict__ mask,
                float*       __restrict__ out)
{
    const long long base = (long long)blockIdx.x * S_LEN;
    const float4* s4 = reinterpret_cast<const float4*>(scores + base);
    const int4*   m4 = reinterpret_cast<const int4*>(mask + base);
    float4*       o4 = reinterpret_cast<float4*>(out + base);

    const int tid  = threadIdx.x;
    const int warp = tid >> 5;
    const int lane = tid & 31;

    // ---- load 16 elems/thread (front-batched), apply mask ----
    float x[EPT];
    #pragma unroll
    for (int v = 0; v < V4; ++v) {
        float4 a = s4[tid + v * THREADS];
        int4   m = m4[tid + v * THREADS];
        x[v * 4 + 0] = m.x ? a.x : NEG_FILL;
        x[v * 4 + 1] = m.y ? a.y : NEG_FILL;
        x[v * 4 + 2] = m.z ? a.z : NEG_FILL;
        x[v * 4 + 3] = m.w ? a.w : NEG_FILL;
    }

    __shared__ float  shmax[WARPS];
    __shared__ float2 red[2][WARPS];   // double-buffered (S1, S2) per warp

    // ---- block max: one barrier, every thread combines the 4 warp maxes ----
    float mx = x[0];
    #pragma unroll
    for (int i = 1; i < EPT; ++i) mx = fmaxf(mx, x[i]);
    #pragma unroll
    for (int o = 16; o; o >>= 1) mx = fmaxf(mx, __shfl_xor_sync(0xffffffffu, mx, o));
    if (lane == 0) shmax[warp] = mx;
    __syncthreads();
    mx = fmaxf(fmaxf(shmax[0], shmax[1]), fmaxf(shmax[2], shmax[3]));

    // ---- alpha=1.5 transform: X = (x - max) * 0.5 so max(X) == 0 ----
    const float mxh = mx * 0.5f;
    #pragma unroll
    for (int i = 0; i < EPT; ++i) x[i] = fmaf(x[i], 0.5f, -mxh);

    // ---- Newton-on-sqrt root find; tau* in [-1, 0) ----
    float tau = -1.0f;   // the max element alone contributes 1 => f(-1) >= 1
    int   p   = 0;

    #pragma unroll 1
    for (int it = 0; it < 20; ++it) {
        float s1a = 0.0f, s1b = 0.0f, s2a = 0.0f, s2b = 0.0f;
        #pragma unroll
        for (int i = 0; i < EPT; i += 2) {
            float d0 = fmaxf(x[i]     - tau, 0.0f);
            float d1 = fmaxf(x[i + 1] - tau, 0.0f);
            s1a += d0;                s1b += d1;
            s2a  = fmaf(d0, d0, s2a); s2b  = fmaf(d1, d1, s2b);
        }
        float s1 = s1a + s1b;
        float s2 = s2a + s2b;
        #pragma unroll
        for (int o = 16; o; o >>= 1) {
            s1 += __shfl_xor_sync(0xffffffffu, s1, o);
            s2 += __shfl_xor_sync(0xffffffffu, s2, o);
        }
        if (lane == 0) red[p][warp] = make_float2(s1, s2);
        __syncthreads();

        float2 r0 = red[p][0], r1 = red[p][1], r2 = red[p][2], r3 = red[p][3];
        float S1 = (r0.x + r1.x) + (r2.x + r3.x);
        float S2 = (r0.y + r1.y) + (r2.y + r3.y);
        p ^= 1;

        // Newton on sqrt(f)-1: dlt = (S2 - sqrt(S2)) / S1.
        // Uniform inputs + uniform ops -> tau identical across all threads.
        float dlt = __fdividef(S2 - sqrtf(S2), fmaxf(S1, 1e-20f));
        tau += dlt;
        if (dlt < 1e-6f) break;
    }

    // ---- emit p = clip(X - tau, 0)^2 ----
    #pragma unroll
    for (int v = 0; v < V4; ++v) {
        float4 r;
        float d;
        d = fmaxf(x[v * 4 + 0] - tau, 0.0f); r.x = d * d;
        d = fmaxf(x[v * 4 + 1] - tau, 0.0f); r.y = d * d;
        d = fmaxf(x[v * 4 + 2] - tau, 0.0f); r.z = d * d;
        d = fmaxf(x[v * 4 + 3] - tau, 0.0f); r.w = d * d;
        o4[tid + v * THREADS] = r;
    }
}

extern "C" void kernel_launch(void* const* d_in, const int* in_sizes, int n_in,
                              void* d_out, int out_size)
{
    const float* scores = (const float*)d_in[0];
    const int*   mask   = (const int*)d_in[1];
    float*       out    = (float*)d_out;
    const int rows = in_sizes[0] / S_LEN;
    entmax15_kernel<<<rows, THREADS>>>(scores, mask, out);
}